// round 9
// baseline (speedup 1.0000x reference)
#include <cuda_runtime.h>
#include <math.h>

// Problem constants
#define CUTN    10
#define DMODES  4
#define BATCH   256
#define NLAYERS 4
#define PW      48
#define NBS     48
#define NSEC    19

#define NTHR    256
#define NITEMS  475           // 19 sectors * 25 four-fiber items

// Padded state strides (float2 units), all odd
#define S0P 1111
#define S1P 111
#define S2P 11
#define S3P 1
#define SSZ (9*S0P + 9*S1P + 9*S2P + 9*S3P + 1)   // 11107 float2

typedef unsigned long long u64;

// ---------------------------------------------------------------------------
__device__ __forceinline__ float2 cmul(float2 a, float2 b) {
    return make_float2(a.x*b.x - a.y*b.y, a.x*b.y + a.y*b.x);
}
__device__ __forceinline__ float2 cfma(float2 a, float2 b, float2 acc) {
    acc.x += a.x*b.x - a.y*b.y;
    acc.y += a.x*b.y + a.y*b.x;
    return acc;
}
__device__ __forceinline__ float2 expi(float a) {
    float s, c; sincosf(a, &s, &c);
    return make_float2(c, s);
}

#define FMA2(acc, a, b) \
    asm("fma.rn.f32x2 %0, %1, %2, %0;" : "+l"(acc) : "l"(a), "l"(b))

// load state amp + apply pending phase (tb = phase dup-packed? no: tb=(pr,pi), tbs=(pi,pr))
__device__ __forceinline__ u64 ldphase(const u64* Su, int a, u64 tb, u64 tbs) {
    float2 v = ((const float2*)Su)[a];
    float nvy = -v.y;
    u64 xx, yy, p = 0ULL;
    asm("mov.b64 %0, {%1, %1};" : "=l"(xx) : "f"(v.x));
    asm("mov.b64 %0, {%1, %2};" : "=l"(yy) : "f"(nvy), "f"(v.y));
    FMA2(p, tb, xx); FMA2(p, tbs, yy);
    return p;
}

// ---------------------------------------------------------------------------
// Device scratch.  Gate matrices REAL, duplicated (R,R) for FMA2.
// ---------------------------------------------------------------------------
__device__ float2 g_bs[NBS][100][10];
__device__ float2 g_sq[16][100];
__device__ float2 g_dp[16][100];
__device__ float2 g_S0[100];
__device__ float2 g_Dm[BATCH*DMODES][100];
__device__ float2 g_psi[BATCH][DMODES][CUTN];

// Pair strides: p over (0,1),(0,2),(0,3),(1,2),(1,3),(2,3)
__constant__ int cSI[6] = {S0P,S0P,S0P,S1P,S1P,S2P};
__constant__ int cSJ[6] = {S1P,S2P,S3P,S2P,S3P,S3P};
__constant__ int cSA[6] = {S2P,S1P,S1P,S0P,S0P,S0P};
__constant__ int cSB[6] = {S3P,S3P,S2P,S3P,S2P,S1P};
__constant__ int cPI[6] = {0,0,0,1,1,2};
__constant__ int cPJ[6] = {1,2,3,2,3,3};
__constant__ int cMS[4] = {S0P,S1P,S2P,S3P};
__constant__ int cR0[4] = {S1P,S0P,S0P,S0P};
__constant__ int cR1[4] = {S2P,S2P,S1P,S1P};
__constant__ int cR2[4] = {S3P,S3P,S3P,S2P};
__constant__ int cD[19] = {1,2,3,4,5,6,7,8,9,10,9,8,7,6,5,4,3,2,1};

// ---------------------------------------------------------------------------
// Kernel 1: build gates (expm). Real generators; phases at runtime.
// ---------------------------------------------------------------------------
#define NJOBS (1 + 1024 + 16 + 16 + NBS*NSEC)

__global__ void build_gates(const float* __restrict__ inputs,
                            const float* __restrict__ w)
{
    __shared__ float2 A[100], E[100], P[100];
    const int job = blockIdx.x;
    const int tid = threadIdx.x;

    int d = CUTN;
    int lo = 0, N = 0, g = 0;
    const bool isBS = (job >= 1057);
    if (isBS) {
        int idx = job - 1057;
        g = idx / NSEC;  N = idx % NSEC;
        lo = max(0, N - (CUTN-1));
        int hi = min(CUTN-1, N);
        d = hi - lo + 1;
    }

    if (tid < d*d) {
        int i = tid / d, j = tid % d;
        float2 v = make_float2(0.f, 0.f);
        if (job == 0) {
            if (i == j-2)      v = make_float2(0.f, -0.25f * sqrtf((float)(j*(j-1))));
            else if (i == j+2) v = make_float2(0.f, -0.25f * sqrtf((float)((j+1)*(j+2))));
        } else if (job <= 1024) {
            float xv = inputs[job-1];
            if (i == j+1)      v = make_float2( xv * sqrtf((float)(j+1)), 0.f);
            else if (i == j-1) v = make_float2(-xv * sqrtf((float)j),     0.f);
        } else if (job <= 1040) {
            int q = job - 1025; int l = q/4, m = q%4;
            float r = w[l*PW + 16 + m];
            if (i == j-2)      v = make_float2( 0.5f*r*sqrtf((float)(j*(j-1))),     0.f);
            else if (i == j+2) v = make_float2(-0.5f*r*sqrtf((float)((j+1)*(j+2))), 0.f);
        } else if (job <= 1056) {
            int q = job - 1041; int l = q/4, m = q%4;
            float rd = w[l*PW + 36 + m];
            if (i == j+1)      v = make_float2( rd * sqrtf((float)(j+1)), 0.f);
            else if (i == j-1) v = make_float2(-rd * sqrtf((float)j),     0.f);
        } else {
            int l = g / 12; int h = (g % 12) / 6; int p = g % 6;
            float th = w[l*PW + (h ? 20 : 0) + p];
            int yi = lo + j; int yj = N - yi;
            if (i == j+1)      v = make_float2( th * sqrtf((float)((yi+1)*yj)), 0.f);
            else if (i == j-1) v = make_float2(-th * sqrtf((float)(yi*(yj+1))), 0.f);
        }
        A[tid] = v;
    }
    __syncthreads();

    const float SC = 1.0f/32.0f;
    if (tid < d*d) {
        int i = tid/d;
        float2 m0 = make_float2(A[tid].x*SC, A[tid].y*SC);
        P[tid] = m0;
        E[tid] = make_float2(((tid % d) == i ? 1.f : 0.f) + m0.x, m0.y);
    }
    __syncthreads();
    for (int k = 2; k <= 8; ++k) {
        float2 t = make_float2(0.f, 0.f);
        if (tid < d*d) {
            int i = tid/d, j = tid%d;
            for (int u = 0; u < d; ++u)
                t = cfma(P[i*d+u], A[u*d+j], t);
            float f = SC / (float)k;
            t.x *= f; t.y *= f;
        }
        __syncthreads();
        if (tid < d*d) {
            E[tid].x += t.x; E[tid].y += t.y;
            P[tid] = t;
        }
        __syncthreads();
    }
    for (int s = 0; s < 5; ++s) {
        float2 t = make_float2(0.f, 0.f);
        if (tid < d*d) {
            int i = tid/d, j = tid%d;
            for (int u = 0; u < d; ++u)
                t = cfma(E[i*d+u], E[u*d+j], t);
        }
        __syncthreads();
        if (tid < d*d) E[tid] = t;
        __syncthreads();
    }

    if (job == 0) {
        if (tid < 100) g_S0[tid] = E[tid];
    } else if (job <= 1024) {
        if (tid < 100) g_Dm[job-1][tid] = E[tid];
    } else if (job <= 1040) {
        if (tid < 100) { float r = E[tid].x; g_sq[job-1025][tid] = make_float2(r, r); }
    } else if (job <= 1056) {
        if (tid < 100) { float r = E[tid].x; g_dp[job-1041][tid] = make_float2(r, r); }
    } else {
        if (tid < d*10) {
            int x = tid/10, t = tid%10;
            int xi = lo + x, xj = N - xi;
            float r = (t < d) ? E[x*d + t].x : 0.f;
            g_bs[g][xi*10 + xj][t] = make_float2(r, r);
        }
    }
}

// ---------------------------------------------------------------------------
// Kernel 2: g_psi[b][m] = Dm[b*4+m] @ S0[:,0]
// ---------------------------------------------------------------------------
__global__ void init_psi()
{
    int t = blockIdx.x * blockDim.x + threadIdx.x;
    if (t >= BATCH*DMODES) return;
    float2 p0[CUTN];
#pragma unroll
    for (int y = 0; y < CUTN; ++y) p0[y] = g_S0[y*CUTN + 0];
    const float2* Dm = g_Dm[t];
#pragma unroll
    for (int i = 0; i < CUTN; ++i) {
        float2 acc = make_float2(0.f, 0.f);
#pragma unroll
        for (int y = 0; y < CUTN; ++y) acc = cfma(Dm[i*CUTN + y], p0[y], acc);
        g_psi[t/DMODES][t%DMODES][i] = acc;
    }
}

// ---------------------------------------------------------------------------
// Circuit kernel: 4-fiber tiles, stride-1 lanes, real gates + pending phases.
// ---------------------------------------------------------------------------
template<int D>
__device__ __forceinline__ void bs_item4(u64* Su, const u64* __restrict__ Ub,
        const u64* __restrict__ tab, const u64* __restrict__ tabs,
        int caddr, int o1, int o2, int ds, int ur0)
{
    u64 in0[D], in1[D], in2[D], in3[D];
#pragma unroll
    for (int t = 0; t < D; ++t) {
        u64 tb = tab[t], tbs = tabs[t];
        int a = caddr + t*ds;
        in0[t] = ldphase(Su, a,       tb, tbs);
        in1[t] = ldphase(Su, a+o1,    tb, tbs);
        in2[t] = ldphase(Su, a+o2,    tb, tbs);
        in3[t] = ldphase(Su, a+o1+o2, tb, tbs);
    }
#pragma unroll
    for (int x = 0; x < D; ++x) {
        const u64* Ur = Ub + ur0 + x*90;
        u64 a0 = 0ULL, a1 = 0ULL, a2 = 0ULL, a3 = 0ULL;
#pragma unroll
        for (int t = 0; t < D; ++t) {
            u64 u = Ur[t];
            FMA2(a0, u, in0[t]); FMA2(a1, u, in1[t]);
            FMA2(a2, u, in2[t]); FMA2(a3, u, in3[t]);
        }
        int a = caddr + x*ds;
        Su[a] = a0; Su[a+o1] = a1; Su[a+o2] = a2; Su[a+o1+o2] = a3;
    }
}

__device__ __forceinline__ void apply_bs(u64* Su, u64* Ub, u64* tab, u64* tabs,
                                         float2* pend, float2* Ai, float2* Aj,
                                         u64 pack, int g, int p, float phi, int tid)
{
    {
        const u64* src = (const u64*)&g_bs[g][0][0];
        for (int q = tid; q < 1000; q += NTHR) Ub[q] = src[q];
    }
    const int mi = cPI[p], mj = cPJ[p];
    if (tid < 10) {
        Ai[tid] = cmul(pend[mi*10 + tid], expi(-phi * (float)tid));
    } else if (tid < 20) {
        int t = tid - 10;
        Aj[t] = pend[mj*10 + t];
    }
    __syncthreads();
    if (tid < 190) {
        int N = tid / 10, t = tid % 10;
        int lo = (N > 9) ? N - 9 : 0;
        int yi = lo + t, yj = N - yi;
        float2 val = make_float2(0.f, 0.f);
        if (yi <= 9 && yj >= 0) val = cmul(Ai[yi], Aj[yj]);
        ((float2*)tab)[tid]  = val;
        ((float2*)tabs)[tid] = make_float2(val.y, val.x);
    } else if (tid >= 192 && tid < 212) {
        int t = tid - 192;
        if (t < 10) pend[mi*10 + t] = expi(phi * (float)t);
        else        pend[mj*10 + (t-10)] = make_float2(1.f, 0.f);
    }
    __syncthreads();

    const int sj = cSJ[p], sa = cSA[p], sb = cSB[p];
    const int ds = cSI[p] - sj;
    const int o1 = 5*sb, o2 = 5*sa;

    for (int k = 0; k < 6; ++k) {
        int it = (int)((pack >> (9*k)) & 511ULL);
        if (it >= NITEMS) break;
        int N  = it / 25;
        int q  = it - N*25;
        int fa0 = q / 5, fb0 = q - fa0*5;
        int lo = (N > 9) ? N - 9 : 0;
        int hi = (N < 9) ? N : 9;
        int d  = hi - lo + 1;
        int caddr = fa0*sa + fb0*sb + N*sj + lo*ds;
        int ur0   = (9*lo + N)*10;
        const u64* tN  = tab  + N*10;
        const u64* tNs = tabs + N*10;
        switch (d) {
            case  1: bs_item4< 1>(Su, Ub, tN, tNs, caddr, o1, o2, ds, ur0); break;
            case  2: bs_item4< 2>(Su, Ub, tN, tNs, caddr, o1, o2, ds, ur0); break;
            case  3: bs_item4< 3>(Su, Ub, tN, tNs, caddr, o1, o2, ds, ur0); break;
            case  4: bs_item4< 4>(Su, Ub, tN, tNs, caddr, o1, o2, ds, ur0); break;
            case  5: bs_item4< 5>(Su, Ub, tN, tNs, caddr, o1, o2, ds, ur0); break;
            case  6: bs_item4< 6>(Su, Ub, tN, tNs, caddr, o1, o2, ds, ur0); break;
            case  7: bs_item4< 7>(Su, Ub, tN, tNs, caddr, o1, o2, ds, ur0); break;
            case  8: bs_item4< 8>(Su, Ub, tN, tNs, caddr, o1, o2, ds, ur0); break;
            case  9: bs_item4< 9>(Su, Ub, tN, tNs, caddr, o1, o2, ds, ur0); break;
            default: bs_item4<10>(Su, Ub, tN, tNs, caddr, o1, o2, ds, ur0); break;
        }
    }
    __syncthreads();
}

__device__ __forceinline__ void apply_single(u64* Su, u64* Ub, u64* tab, u64* tabs,
                                             float2* pend, const float2* Ug,
                                             int m, float phi, bool has_phi, int tid)
{
    {
        const u64* src = (const u64*)Ug;
        for (int q = tid; q < 100; q += NTHR) Ub[q] = src[q];
    }
    if (tid < 10) {
        float2 val = pend[m*10 + tid];
        if (has_phi) val = cmul(val, expi(-phi * (float)tid));
        ((float2*)tab)[tid]  = val;
        ((float2*)tabs)[tid] = make_float2(val.y, val.x);
        pend[m*10 + tid] = has_phi ? expi(phi * (float)tid) : make_float2(1.f, 0.f);
    }
    __syncthreads();

    if (tid < 250) {
        const int sm = cMS[m], r0 = cR0[m], r1 = cR1[m], r2 = cR2[m];
        int q  = tid;
        int f0 = q / 50;
        int rm = q - f0*50;
        int f1 = rm / 5, f2 = rm - f1*5;
        int base = f0*r0 + f1*r1 + f2*r2;
        int o1 = 5*r2, o2 = 5*r0;

        u64 in0[10], in1[10], in2[10], in3[10];
#pragma unroll
        for (int y = 0; y < 10; ++y) {
            u64 tb = tab[y], tbs = tabs[y];
            int a = base + y*sm;
            in0[y] = ldphase(Su, a,       tb, tbs);
            in1[y] = ldphase(Su, a+o1,    tb, tbs);
            in2[y] = ldphase(Su, a+o2,    tb, tbs);
            in3[y] = ldphase(Su, a+o1+o2, tb, tbs);
        }
#pragma unroll
        for (int x = 0; x < 10; ++x) {
            const u64* Ur = Ub + x*10;
            u64 a0 = 0ULL, a1 = 0ULL, a2 = 0ULL, a3 = 0ULL;
#pragma unroll
            for (int y = 0; y < 10; ++y) {
                u64 u = Ur[y];
                FMA2(a0, u, in0[y]); FMA2(a1, u, in1[y]);
                FMA2(a2, u, in2[y]); FMA2(a3, u, in3[y]);
            }
            int a = base + x*sm;
            Su[a] = a0; Su[a+o1] = a1; Su[a+o2] = a2; Su[a+o1+o2] = a3;
        }
    }
    __syncthreads();
}

__global__ void __launch_bounds__(NTHR, 2)
circuit(const float* __restrict__ w, float* __restrict__ out)
{
    extern __shared__ float2 sh[];
    float2* S    = sh;                    // 11107
    float2* UbF  = sh + SSZ;              // 1000
    float2* tabF = sh + SSZ + 1000;       // 190
    float2* tbsF = sh + SSZ + 1190;       // 190
    float2* pend = sh + SSZ + 1380;       // 40
    float2* Ai   = sh + SSZ + 1420;       // 10
    float2* Aj   = sh + SSZ + 1430;       // 10
    float2* PV   = sh + SSZ + 1440;       // 40
    __shared__ float red[8*4];

    const int b = blockIdx.x, tid = threadIdx.x;
    const int wid = tid >> 5, lane = tid & 31;
    u64* Su  = (u64*)S;
    u64* Ub  = (u64*)UbF;
    u64* tab = (u64*)tabF;
    u64* tbs = (u64*)tbsF;

    // ---- per-thread BS item list (weight-balanced warp partition), packed
    u64 pack = ~0ULL;   // 9-bit slots, sentinel 511
    {
        int wN[19]; long long W = 0;
        for (int N = 0; N < 19; ++N) {
            int d = cD[N];
            wN[N] = 5*d*d + 16*d + 12;
            W += 25LL * wN[N];
        }
        long long t0 = (long long)wid * W / 8;
        long long t1 = (long long)(wid + 1) * W / 8;
        int it0 = 0, it1 = 0;
        {
            long long cum = 0; int it = 0; bool done = false;
            for (int N = 0; N < 19 && !done; ++N) {
                long long sw = 25LL * wN[N];
                if (cum + sw <= t0) { cum += sw; it += 25; }
                else { it += (int)((t0 - cum) / wN[N]); done = true; }
            }
            it0 = it;
        }
        {
            long long cum = 0; int it = 0; bool done = false;
            for (int N = 0; N < 19 && !done; ++N) {
                long long sw = 25LL * wN[N];
                if (cum + sw <= t1) { cum += sw; it += 25; }
                else { it += (int)((t1 - cum) / wN[N]); done = true; }
            }
            it1 = it;
        }
        int n = 0;
        for (int it = it0 + lane; it < it1 && n < 6; it += 32, ++n)
            pack = (pack & ~(511ULL << (9*n))) | ((u64)it << (9*n));
    }

    // ---- initial product state + identity pending phases
    if (tid >= 64 && tid < 104) {
        int t = tid - 64;
        PV[t]   = g_psi[b][t/10][t%10];
        pend[t] = make_float2(1.f, 0.f);
    }
    __syncthreads();
    for (int o = tid; o < 10000; o += NTHR) {
        int i = o/1000, j = (o/100)%10, kk = (o/10)%10, l = o%10;
        S[o + i*111 + j*11 + kk] = cmul(cmul(PV[i], PV[10+j]), cmul(PV[20+kk], PV[30+l]));
    }
    __syncthreads();

    for (int lay = 0; lay < NLAYERS; ++lay) {
        const float* wl = w + lay*PW;
        for (int p = 0; p < 6; ++p)
            apply_bs(Su, Ub, tab, tbs, pend, Ai, Aj, pack, lay*12 + p, p, wl[6+p], tid);
        if (tid < 40) {
            int m = tid/10, n = tid%10;
            pend[tid] = cmul(pend[tid], expi(wl[12+m] * (float)n));
        }
        __syncthreads();
        for (int m = 0; m < 4; ++m)
            apply_single(Su, Ub, tab, tbs, pend, g_sq[lay*4 + m], m, 0.f, false, tid);
        for (int p = 0; p < 6; ++p)
            apply_bs(Su, Ub, tab, tbs, pend, Ai, Aj, pack, lay*12 + 6 + p, p, wl[26+p], tid);
        if (tid < 40) {
            int m = tid/10, n = tid%10;
            pend[tid] = cmul(pend[tid], expi(wl[32+m] * (float)n));
        }
        __syncthreads();
        for (int m = 0; m < 4; ++m)
            apply_single(Su, Ub, tab, tbs, pend, g_dp[lay*4 + m], m, wl[40+m], true, tid);
        if (tid < 40) {
            int m = tid/10, n = tid%10;
            pend[tid] = cmul(pend[tid], expi(wl[44+m] * (float)(n*n)));
        }
        __syncthreads();
    }
    // final pending phases are diagonal -> invisible in |psi|^2

    // <n_m> readout
    float a0 = 0.f, a1 = 0.f, a2 = 0.f, a3 = 0.f;
    for (int o = tid; o < 10000; o += NTHR) {
        int i = o/1000, j = (o/100)%10, kk = (o/10)%10, l = o%10;
        float2 s = S[o + i*111 + j*11 + kk];
        float pr = s.x*s.x + s.y*s.y;
        a0 += pr * (float)i;
        a1 += pr * (float)j;
        a2 += pr * (float)kk;
        a3 += pr * (float)l;
    }
#pragma unroll
    for (int off = 16; off > 0; off >>= 1) {
        a0 += __shfl_down_sync(0xffffffffu, a0, off);
        a1 += __shfl_down_sync(0xffffffffu, a1, off);
        a2 += __shfl_down_sync(0xffffffffu, a2, off);
        a3 += __shfl_down_sync(0xffffffffu, a3, off);
    }
    if (lane == 0) {
        red[wid*4 + 0] = a0; red[wid*4 + 1] = a1;
        red[wid*4 + 2] = a2; red[wid*4 + 3] = a3;
    }
    __syncthreads();
    if (tid < 4) {
        float s = 0.f;
        for (int ww = 0; ww < 8; ++ww) s += red[ww*4 + tid];
        out[b*4 + tid] = s;
    }
}

// ---------------------------------------------------------------------------
#define CIRCUIT_SMEM ((SSZ + 1480) * (int)sizeof(float2))   // 100,696 B

extern "C" void kernel_launch(void* const* d_in, const int* in_sizes, int n_in,
                              void* d_out, int out_size)
{
    const float* inputs  = (const float*)d_in[0];
    const float* weights = (const float*)d_in[1];
    float* out = (float*)d_out;

    cudaFuncSetAttribute(circuit, cudaFuncAttributeMaxDynamicSharedMemorySize, CIRCUIT_SMEM);

    build_gates<<<NJOBS, 128>>>(inputs, weights);
    init_psi<<<4, 256>>>();
    circuit<<<BATCH, NTHR, CIRCUIT_SMEM>>>(weights, out);
}

// round 11
// speedup vs baseline: 1.5074x; 1.5074x over previous
#include <cuda_runtime.h>
#include <math.h>

// Problem constants
#define CUTN    10
#define DMODES  4
#define BATCH   256
#define NLAYERS 4
#define PW      48
#define NBS     48
#define NSEC    19

#define NTHR    256

// Padded state strides (float2 units), all odd -> conflict-light LDS
#define S0P 1111
#define S1P 111
#define S2P 11
#define S3P 1
#define SSZ (9*S0P + 9*S1P + 9*S2P + 9*S3P + 1)   // 11107 float2

typedef unsigned long long u64;

// ---------------------------------------------------------------------------
__device__ __forceinline__ float2 cmul(float2 a, float2 b) {
    return make_float2(a.x*b.x - a.y*b.y, a.x*b.y + a.y*b.x);
}
__device__ __forceinline__ float2 cfma(float2 a, float2 b, float2 acc) {
    acc.x += a.x*b.x - a.y*b.y;
    acc.y += a.x*b.y + a.y*b.x;
    return acc;
}
__device__ __forceinline__ float2 expi(float a) {
    float s, c; sincosf(a, &s, &c);
    return make_float2(c, s);
}

#define FMA2(acc, a, b) \
    asm("fma.rn.f32x2 %0, %1, %2, %0;" : "+l"(acc) : "l"(a), "l"(b))

__device__ __forceinline__ u64 ldphase(const u64* Su, int a, u64 tb, u64 tbs) {
    float2 v = ((const float2*)Su)[a];
    float nvy = -v.y;
    u64 xx, yy, p = 0ULL;
    asm("mov.b64 %0, {%1, %1};" : "=l"(xx) : "f"(v.x));
    asm("mov.b64 %0, {%1, %2};" : "=l"(yy) : "f"(nvy), "f"(v.y));
    FMA2(p, tb, xx); FMA2(p, tbs, yy);
    return p;
}

// ---------------------------------------------------------------------------
// Device scratch.  All gate matrices REAL, duplicated (R,R) for FMA2.
// ---------------------------------------------------------------------------
__device__ float2 g_bs[NBS][100][10];
__device__ float2 g_sq[16][100];
__device__ float2 g_dp[16][100];
__device__ float2 g_S0[100];
__device__ float2 g_Dm[BATCH*DMODES][100];
__device__ float2 g_psi[BATCH][DMODES][CUTN];

// Pair strides: p over (0,1),(0,2),(0,3),(1,2),(1,3),(2,3)
__constant__ int cSI[6] = {S0P,S0P,S0P,S1P,S1P,S2P};
__constant__ int cSJ[6] = {S1P,S2P,S3P,S2P,S3P,S3P};
__constant__ int cSA[6] = {S2P,S1P,S1P,S0P,S0P,S0P};
__constant__ int cSB[6] = {S3P,S3P,S2P,S3P,S2P,S1P};
__constant__ int cPI[6] = {0,0,0,1,1,2};
__constant__ int cPJ[6] = {1,2,3,2,3,3};
__constant__ int cMS[4] = {S0P,S1P,S2P,S3P};
__constant__ int cR0[4] = {S1P,S0P,S0P,S0P};
__constant__ int cR1[4] = {S2P,S2P,S1P,S1P};
__constant__ int cR2[4] = {S3P,S3P,S3P,S2P};

// ---------------------------------------------------------------------------
// Kernel 1: build gates (expm). Real generators; phases at runtime.
// ---------------------------------------------------------------------------
#define NJOBS (1 + 1024 + 16 + 16 + NBS*NSEC)

__global__ void build_gates(const float* __restrict__ inputs,
                            const float* __restrict__ w)
{
    __shared__ float2 A[100], E[100], P[100];
    const int job = blockIdx.x;
    const int tid = threadIdx.x;

    int d = CUTN;
    int lo = 0, N = 0, g = 0;
    const bool isBS = (job >= 1057);
    if (isBS) {
        int idx = job - 1057;
        g = idx / NSEC;  N = idx % NSEC;
        lo = max(0, N - (CUTN-1));
        int hi = min(CUTN-1, N);
        d = hi - lo + 1;
    }

    if (tid < d*d) {
        int i = tid / d, j = tid % d;
        float2 v = make_float2(0.f, 0.f);
        if (job == 0) {
            if (i == j-2)      v = make_float2(0.f, -0.25f * sqrtf((float)(j*(j-1))));
            else if (i == j+2) v = make_float2(0.f, -0.25f * sqrtf((float)((j+1)*(j+2))));
        } else if (job <= 1024) {
            float xv = inputs[job-1];
            if (i == j+1)      v = make_float2( xv * sqrtf((float)(j+1)), 0.f);
            else if (i == j-1) v = make_float2(-xv * sqrtf((float)j),     0.f);
        } else if (job <= 1040) {
            int q = job - 1025; int l = q/4, m = q%4;
            float r = w[l*PW + 16 + m];
            if (i == j-2)      v = make_float2( 0.5f*r*sqrtf((float)(j*(j-1))),     0.f);
            else if (i == j+2) v = make_float2(-0.5f*r*sqrtf((float)((j+1)*(j+2))), 0.f);
        } else if (job <= 1056) {
            int q = job - 1041; int l = q/4, m = q%4;
            float rd = w[l*PW + 36 + m];
            if (i == j+1)      v = make_float2( rd * sqrtf((float)(j+1)), 0.f);
            else if (i == j-1) v = make_float2(-rd * sqrtf((float)j),     0.f);
        } else {
            int l = g / 12; int h = (g % 12) / 6; int p = g % 6;
            float th = w[l*PW + (h ? 20 : 0) + p];
            int yi = lo + j; int yj = N - yi;
            if (i == j+1)      v = make_float2( th * sqrtf((float)((yi+1)*yj)), 0.f);
            else if (i == j-1) v = make_float2(-th * sqrtf((float)(yi*(yj+1))), 0.f);
        }
        A[tid] = v;
    }
    __syncthreads();

    const float SC = 1.0f/32.0f;
    if (tid < d*d) {
        int i = tid/d;
        float2 m0 = make_float2(A[tid].x*SC, A[tid].y*SC);
        P[tid] = m0;
        E[tid] = make_float2(((tid % d) == i ? 1.f : 0.f) + m0.x, m0.y);
    }
    __syncthreads();
    for (int k = 2; k <= 8; ++k) {
        float2 t = make_float2(0.f, 0.f);
        if (tid < d*d) {
            int i = tid/d, j = tid%d;
            for (int u = 0; u < d; ++u)
                t = cfma(P[i*d+u], A[u*d+j], t);
            float f = SC / (float)k;
            t.x *= f; t.y *= f;
        }
        __syncthreads();
        if (tid < d*d) {
            E[tid].x += t.x; E[tid].y += t.y;
            P[tid] = t;
        }
        __syncthreads();
    }
    for (int s = 0; s < 5; ++s) {
        float2 t = make_float2(0.f, 0.f);
        if (tid < d*d) {
            int i = tid/d, j = tid%d;
            for (int u = 0; u < d; ++u)
                t = cfma(E[i*d+u], E[u*d+j], t);
        }
        __syncthreads();
        if (tid < d*d) E[tid] = t;
        __syncthreads();
    }

    if (job == 0) {
        if (tid < 100) g_S0[tid] = E[tid];
    } else if (job <= 1024) {
        if (tid < 100) g_Dm[job-1][tid] = E[tid];
    } else if (job <= 1040) {
        if (tid < 100) { float r = E[tid].x; g_sq[job-1025][tid] = make_float2(r, r); }
    } else if (job <= 1056) {
        if (tid < 100) { float r = E[tid].x; g_dp[job-1041][tid] = make_float2(r, r); }
    } else {
        if (tid < d*10) {
            int x = tid/10, t = tid%10;
            int xi = lo + x, xj = N - xi;
            float r = (t < d) ? E[x*d + t].x : 0.f;
            g_bs[g][xi*10 + xj][t] = make_float2(r, r);
        }
    }
}

// ---------------------------------------------------------------------------
// Kernel 2: g_psi[b][m] = Dm[b*4+m] @ S0[:,0]
// ---------------------------------------------------------------------------
__global__ void init_psi()
{
    int t = blockIdx.x * blockDim.x + threadIdx.x;
    if (t >= BATCH*DMODES) return;
    float2 p0[CUTN];
#pragma unroll
    for (int y = 0; y < CUTN; ++y) p0[y] = g_S0[y*CUTN + 0];
    const float2* Dm = g_Dm[t];
#pragma unroll
    for (int i = 0; i < CUTN; ++i) {
        float2 acc = make_float2(0.f, 0.f);
#pragma unroll
        for (int y = 0; y < CUTN; ++y) acc = cfma(Dm[i*CUTN + y], p0[y], acc);
        g_psi[t/DMODES][t%DMODES][i] = acc;
    }
}

// ---------------------------------------------------------------------------
// Circuit kernel: 2-fiber tiles paired along the LARGE-stride fiber axis
// (pair offset 5*sa / 5*r0) with lanes consecutive along the SMALL-stride
// axis -> conflict-light state LDS; real gates + pending phases.
// ---------------------------------------------------------------------------
template<int D>
__device__ __forceinline__ void bs_item2(u64* Su, const u64* __restrict__ Ub,
        const u64* __restrict__ tab, const u64* __restrict__ tabs,
        int caddr, int po, int ds, int ur0)
{
    u64 inA[D], inB[D];
#pragma unroll
    for (int t = 0; t < D; ++t) {
        u64 tb = tab[t], tbs = tabs[t];
        int a = caddr + t*ds;
        inA[t] = ldphase(Su, a,      tb, tbs);
        inB[t] = ldphase(Su, a + po, tb, tbs);
    }
#pragma unroll
    for (int x = 0; x < D; ++x) {
        const u64* Ur = Ub + ur0 + x*90;
        u64 aA = 0ULL, aB = 0ULL;
#pragma unroll
        for (int t = 0; t < D; ++t) {
            u64 u = Ur[t];
            FMA2(aA, u, inA[t]);
            FMA2(aB, u, inB[t]);
        }
        int a = caddr + x*ds;
        Su[a]      = aA;
        Su[a + po] = aB;
    }
}

__device__ __forceinline__ void apply_bs(u64* Su, u64* Ub, u64* tab, u64* tabs,
                                         float2* pend, float2* Ai, float2* Aj,
                                         const int* istart,
                                         int g, int p, float phi, int tid)
{
    {
        const u64* src = (const u64*)&g_bs[g][0][0];
        for (int q = tid; q < 1000; q += NTHR) Ub[q] = src[q];
    }
    const int mi = cPI[p], mj = cPJ[p];
    if (tid < 10) {
        Ai[tid] = cmul(pend[mi*10 + tid], expi(-phi * (float)tid));
    } else if (tid < 20) {
        int t = tid - 10;
        Aj[t] = pend[mj*10 + t];
    }
    __syncthreads();
    if (tid < 190) {
        int N = tid / 10, t = tid % 10;
        int lo = (N > 9) ? N - 9 : 0;
        int yi = lo + t, yj = N - yi;
        float2 val = make_float2(0.f, 0.f);
        if (yi <= 9 && yj >= 0) val = cmul(Ai[yi], Aj[yj]);
        ((float2*)tab)[tid]  = val;
        ((float2*)tabs)[tid] = make_float2(val.y, val.x);
    } else if (tid >= 192 && tid < 212) {
        int t = tid - 192;
        if (t < 10) pend[mi*10 + t] = expi(phi * (float)t);
        else        pend[mj*10 + (t-10)] = make_float2(1.f, 0.f);
    }
    __syncthreads();

    const int sj = cSJ[p], sa = cSA[p], sb = cSB[p];
    const int ds = cSI[p] - sj;
    const int po = 5*sa;
    const int wid = tid >> 5, lane = tid & 31;
    const int i1 = istart[wid+1];

    for (int it = istart[wid] + lane; it < i1; it += 32) {
        int N   = it / 50;
        int q   = it - N*50;
        int fa0 = q / 10, fb = q - fa0*10;
        int base = fa0*sa + fb*sb;
        int lo = (N > 9) ? N - 9 : 0;
        int hi = (N < 9) ? N : 9;
        int d  = hi - lo + 1;
        int caddr = base + N*sj + lo*ds;
        int ur0   = (9*lo + N)*10;
        const u64* tN  = tab  + N*10;
        const u64* tNs = tabs + N*10;
        switch (d) {
            case  1: bs_item2< 1>(Su, Ub, tN, tNs, caddr, po, ds, ur0); break;
            case  2: bs_item2< 2>(Su, Ub, tN, tNs, caddr, po, ds, ur0); break;
            case  3: bs_item2< 3>(Su, Ub, tN, tNs, caddr, po, ds, ur0); break;
            case  4: bs_item2< 4>(Su, Ub, tN, tNs, caddr, po, ds, ur0); break;
            case  5: bs_item2< 5>(Su, Ub, tN, tNs, caddr, po, ds, ur0); break;
            case  6: bs_item2< 6>(Su, Ub, tN, tNs, caddr, po, ds, ur0); break;
            case  7: bs_item2< 7>(Su, Ub, tN, tNs, caddr, po, ds, ur0); break;
            case  8: bs_item2< 8>(Su, Ub, tN, tNs, caddr, po, ds, ur0); break;
            case  9: bs_item2< 9>(Su, Ub, tN, tNs, caddr, po, ds, ur0); break;
            default: bs_item2<10>(Su, Ub, tN, tNs, caddr, po, ds, ur0); break;
        }
    }
    __syncthreads();
}

__device__ __forceinline__ void apply_single(u64* Su, u64* Ub, u64* tab, u64* tabs,
                                             float2* pend, const float2* Ug,
                                             int m, float phi, bool has_phi, int tid)
{
    {
        const u64* src = (const u64*)Ug;
        for (int q = tid; q < 100; q += NTHR) Ub[q] = src[q];
    }
    if (tid < 10) {
        float2 val = pend[m*10 + tid];
        if (has_phi) val = cmul(val, expi(-phi * (float)tid));
        ((float2*)tab)[tid]  = val;
        ((float2*)tabs)[tid] = make_float2(val.y, val.x);
        pend[m*10 + tid] = has_phi ? expi(phi * (float)tid) : make_float2(1.f, 0.f);
    }
    __syncthreads();

    const int sm = cMS[m], r0 = cR0[m], r1 = cR1[m], r2 = cR2[m];
    const int po = 5*r0;

    for (int it = tid; it < 500; it += NTHR) {
        int f0 = it / 100;
        int rm = it - f0*100;
        int f1 = rm / 10, f2 = rm - f1*10;
        int base = f0*r0 + f1*r1 + f2*r2;
        u64 inA[10], inB[10];
#pragma unroll
        for (int y = 0; y < 10; ++y) {
            u64 tb = tab[y], tbs = tabs[y];
            int a = base + y*sm;
            inA[y] = ldphase(Su, a,      tb, tbs);
            inB[y] = ldphase(Su, a + po, tb, tbs);
        }
#pragma unroll
        for (int x = 0; x < 10; ++x) {
            const u64* Ur = Ub + x*10;
            u64 aA = 0ULL, aB = 0ULL;
#pragma unroll
            for (int y = 0; y < 10; ++y) {
                u64 u = Ur[y];
                FMA2(aA, u, inA[y]);
                FMA2(aB, u, inB[y]);
            }
            int a = base + x*sm;
            Su[a]      = aA;
            Su[a + po] = aB;
        }
    }
    __syncthreads();
}

__global__ void __launch_bounds__(NTHR, 2)
circuit(const float* __restrict__ w, float* __restrict__ out)
{
    extern __shared__ float2 sh[];
    float2* S    = sh;                    // 11107
    float2* UbF  = sh + SSZ;              // 1000
    float2* tabF = sh + SSZ + 1000;       // 190
    float2* tbsF = sh + SSZ + 1190;       // 190
    float2* pend = sh + SSZ + 1380;       // 40
    float2* Ai   = sh + SSZ + 1420;       // 10
    float2* Aj   = sh + SSZ + 1430;       // 10
    float2* PV   = sh + SSZ + 1440;       // 40
    __shared__ int istart[9];
    __shared__ float red[8*4];

    const int b = blockIdx.x, tid = threadIdx.x;
    u64* Su  = (u64*)S;
    u64* Ub  = (u64*)UbF;
    u64* tab = (u64*)tabF;
    u64* tbs = (u64*)tbsF;

    // balanced warp partition of the 950 2-fiber BS items (static weights)
    if (tid < 9) {
        int wn[19]; long long W = 0;
        for (int N = 0; N < 19; ++N) {
            int d = min(min(N + 1, 19 - N), 10);
            wn[N] = 50 * (2*d*d + 8*d + 10);
            W += wn[N];
        }
        long long tw = (long long)tid * W / 8;
        int N = 0; long long cum = 0;
        while (N < 18 && cum + wn[N] <= tw) { cum += wn[N]; N++; }
        int d = min(min(N + 1, 19 - N), 10);
        int k = (int)((tw - cum) / (2*d*d + 8*d + 10));
        if (k > 50) k = 50;
        istart[tid] = N*50 + k;
    }
    // initial product state + identity pending phases
    if (tid >= 16 && tid < 56) {
        int t = tid - 16;
        PV[t]   = g_psi[b][t/10][t%10];
        pend[t] = make_float2(1.f, 0.f);
    }
    __syncthreads();
    for (int o = tid; o < 10000; o += NTHR) {
        int i = o/1000, j = (o/100)%10, kk = (o/10)%10, l = o%10;
        S[o + i*111 + j*11 + kk] = cmul(cmul(PV[i], PV[10+j]), cmul(PV[20+kk], PV[30+l]));
    }
    __syncthreads();

    for (int lay = 0; lay < NLAYERS; ++lay) {
        const float* wl = w + lay*PW;
        for (int p = 0; p < 6; ++p)
            apply_bs(Su, Ub, tab, tbs, pend, Ai, Aj, istart, lay*12 + p, p, wl[6+p], tid);
        if (tid < 40) {
            int m = tid/10, n = tid%10;
            pend[tid] = cmul(pend[tid], expi(wl[12+m] * (float)n));
        }
        __syncthreads();
        for (int m = 0; m < 4; ++m)
            apply_single(Su, Ub, tab, tbs, pend, g_sq[lay*4 + m], m, 0.f, false, tid);
        for (int p = 0; p < 6; ++p)
            apply_bs(Su, Ub, tab, tbs, pend, Ai, Aj, istart, lay*12 + 6 + p, p, wl[26+p], tid);
        if (tid < 40) {
            int m = tid/10, n = tid%10;
            pend[tid] = cmul(pend[tid], expi(wl[32+m] * (float)n));
        }
        __syncthreads();
        for (int m = 0; m < 4; ++m)
            apply_single(Su, Ub, tab, tbs, pend, g_dp[lay*4 + m], m, wl[40+m], true, tid);
        if (tid < 40) {
            int m = tid/10, n = tid%10;
            pend[tid] = cmul(pend[tid], expi(wl[44+m] * (float)(n*n)));
        }
        __syncthreads();
    }
    // final pending phases are diagonal -> invisible in |psi|^2

    // <n_m> readout
    float a0 = 0.f, a1 = 0.f, a2 = 0.f, a3 = 0.f;
    for (int o = tid; o < 10000; o += NTHR) {
        int i = o/1000, j = (o/100)%10, kk = (o/10)%10, l = o%10;
        float2 s = S[o + i*111 + j*11 + kk];
        float pr = s.x*s.x + s.y*s.y;
        a0 += pr * (float)i;
        a1 += pr * (float)j;
        a2 += pr * (float)kk;
        a3 += pr * (float)l;
    }
#pragma unroll
    for (int off = 16; off > 0; off >>= 1) {
        a0 += __shfl_down_sync(0xffffffffu, a0, off);
        a1 += __shfl_down_sync(0xffffffffu, a1, off);
        a2 += __shfl_down_sync(0xffffffffu, a2, off);
        a3 += __shfl_down_sync(0xffffffffu, a3, off);
    }
    int wid = tid / 32, lane = tid % 32;
    if (lane == 0) {
        red[wid*4 + 0] = a0; red[wid*4 + 1] = a1;
        red[wid*4 + 2] = a2; red[wid*4 + 3] = a3;
    }
    __syncthreads();
    if (tid < 4) {
        float s = 0.f;
        for (int ww = 0; ww < 8; ++ww) s += red[ww*4 + tid];
        out[b*4 + tid] = s;
    }
}

// ---------------------------------------------------------------------------
#define CIRCUIT_SMEM ((SSZ + 1480) * (int)sizeof(float2))   // 100,696 B

extern "C" void kernel_launch(void* const* d_in, const int* in_sizes, int n_in,
                              void* d_out, int out_size)
{
    const float* inputs  = (const float*)d_in[0];
    const float* weights = (const float*)d_in[1];
    float* out = (float*)d_out;

    cudaFuncSetAttribute(circuit, cudaFuncAttributeMaxDynamicSharedMemorySize, CIRCUIT_SMEM);

    build_gates<<<NJOBS, 128>>>(inputs, weights);
    init_psi<<<4, 256>>>();
    circuit<<<BATCH, NTHR, CIRCUIT_SMEM>>>(weights, out);
}